// round 8
// baseline (speedup 1.0000x reference)
#include <cuda_runtime.h>

#define NEG_PENALTY 0.03f
#define BATCH 64
#define NCLS  2048
#define LL    1024
#define NT    256
#define SPLIT 4                       // CTAs per batch (split over negs)
#define GRID  (BATCH * SPLIT)
#define FULLM 0xffffffffu
#define POS_PAD 8.0f                  // > any x+PEN  -> max(x,8)-8 == 0 exactly
#define NEG_PAD -1e30f                // max(NEG_PAD+PEN,p)-p == 0 exactly

__device__ float    g_partial[GRID];
__device__ unsigned g_ticket = 0;     // self-resetting via atomicInc wrap

__global__ __launch_bounds__(NT)
void ranking_loss_kernel(const float* __restrict__ ranks,
                         const int*   __restrict__ labels,
                         const void*  __restrict__ ids_raw,
                         float* __restrict__ out)
{
    __shared__ __align__(16) float s_pos[LL + 8];
    __shared__ __align__(16) float s_neg[LL + 8];
    __shared__ int s_pcnt[32];        // pos count per 32-elem round
    __shared__ int s_pexc[32];        // exclusive prefix of counts
    __shared__ float s_warp[8];
    __shared__ int s_np;

    const int b    = blockIdx.x >> 2;   // batch
    const int part = blockIdx.x & 3;    // which quarter of negs this CTA owns
    const int tid  = threadIdx.x;
    const int lane = tid & 31;
    const int wid  = tid >> 5;          // 0..7

    // --- dtype sniff: int64 ids have zero high words at odd 32-bit indices ---
    const int* w32 = (const int*)ids_raw;
    const bool is64 = ((w32[201] | w32[401] | w32[601] | w32[801]) == 0);
    const long long* w64 = (const long long*)ids_raw;

    // ---- gather 4 elems/thread (high MLP, all loads independent) ----
    const float* rrow = ranks  + b * NCLS;
    const int*   lrow = labels + b * NCLS;
    float r[4]; int lb[4];
    #pragma unroll
    for (int e = 0; e < 4; e++) {
        int idx = tid + e * NT;
        int id  = is64 ? (int)w64[idx] : w32[idx];
        r[e]  = __ldg(&rrow[id]);
        lb[e] = __ldg(&lrow[id]);
    }

    // ---- deterministic index-ordered partition (rounds = wid + 8e) ----
    unsigned m[4];
    #pragma unroll
    for (int e = 0; e < 4; e++) {
        m[e] = __ballot_sync(FULLM, lb[e] == 1);
        if (lane == 0) s_pcnt[wid + 8 * e] = __popc(m[e]);
    }
    __syncthreads();
    if (wid == 0) {                   // exclusive scan of 32 round counts
        int c = s_pcnt[lane];
        int inc = c;
        #pragma unroll
        for (int d = 1; d < 32; d <<= 1) {
            int t = __shfl_up_sync(FULLM, inc, d);
            if (lane >= d) inc += t;
        }
        s_pexc[lane] = inc - c;
        if (lane == 31) s_np = inc;
    }
    __syncthreads();

    const int np = s_np;
    const int nn = LL - np;
    const unsigned ltmask = (1u << lane) - 1u;
    #pragma unroll
    for (int e = 0; e < 4; e++) {
        int rnd = wid + 8 * e;
        int rlt = __popc(m[e] & ltmask);
        int bp  = s_pexc[rnd];
        int bn  = rnd * 32 - bp;
        if (lb[e] == 1) s_pos[bp + rlt]          = r[e];
        else            s_neg[bn + (lane - rlt)] = r[e];
    }

    // pads
    const int np4 = (np + 3) & ~3;
    if (tid < np4 - np) s_pos[np + tid] = POS_PAD;

    const int share = (((nn + SPLIT - 1) / SPLIT) + 3) & ~3;  // 16B-aligned starts
    const int start = part * share;
    int count = nn - start;
    if (count > share) count = share;
    if (count < 0)     count = 0;
    const int count4 = (count + 3) & ~3;
    if (tid < count4 - count) s_neg[start + count + tid] = NEG_PAD;
    __syncthreads();

    // ---- dense pair eval: acc = sum(max(x',p)) - 4*sum(p) over own tile ----
    // 256 threads = 32 neg-groups (4 negs) x 8 pos-chunks.
    // pq is warp-uniform -> pos LDS.128 is a pure 32-lane broadcast.
    const int jt = tid & 31;
    const int pq = tid >> 5;             // 0..7
    const int g  = np4 >> 2;             // # float4 pos groups
    const int cg = (g + 7) >> 3;         // groups per chunk
    const int g0 = min(pq * cg, g);
    const int g1 = min(g0 + cg, g);
    const float4* pos4 = (const float4*)s_pos;

    float acc = 0.0f;
    for (int j = (jt << 2); j < count4; j += 128) {
        float4 xq = *(const float4*)(s_neg + start + j);
        float x0 = xq.x + NEG_PENALTY;
        float x1 = xq.y + NEG_PENALTY;
        float x2 = xq.z + NEG_PENALTY;
        float x3 = xq.w + NEG_PENALTY;
        float a0 = 0.0f, a1 = 0.0f, a2 = 0.0f, a3 = 0.0f, ps = 0.0f;
        for (int gi = g0; gi < g1; gi++) {
            float4 q = pos4[gi];
            a0 += fmaxf(x0, q.x); a1 += fmaxf(x1, q.x);
            a2 += fmaxf(x2, q.x); a3 += fmaxf(x3, q.x);
            a0 += fmaxf(x0, q.y); a1 += fmaxf(x1, q.y);
            a2 += fmaxf(x2, q.y); a3 += fmaxf(x3, q.y);
            a0 += fmaxf(x0, q.z); a1 += fmaxf(x1, q.z);
            a2 += fmaxf(x2, q.z); a3 += fmaxf(x3, q.z);
            a0 += fmaxf(x0, q.w); a1 += fmaxf(x1, q.w);
            a2 += fmaxf(x2, q.w); a3 += fmaxf(x3, q.w);
            ps += (q.x + q.y) + (q.z + q.w);
        }
        acc += ((a0 + a1) + (a2 + a3)) - 4.0f * ps;
    }

    // ---- block reduce (8 warps) ----
    #pragma unroll
    for (int d = 16; d >= 1; d >>= 1)
        acc += __shfl_down_sync(FULLM, acc, d);
    if (lane == 0) s_warp[wid] = acc;
    __syncthreads();
    if (wid == 0) {
        float a2r = (lane < 8) ? s_warp[lane] : 0.0f;
        #pragma unroll
        for (int d = 4; d >= 1; d >>= 1)
            a2r += __shfl_down_sync(FULLM, a2r, d);
        int is_last = 0;
        if (lane == 0) {
            g_partial[blockIdx.x] = a2r;
            __threadfence();
            unsigned t = atomicInc(&g_ticket, GRID - 1);   // wraps at 255
            is_last = (t == GRID - 1);
        }
        is_last = __shfl_sync(FULLM, is_last, 0);
        // last CTA reduces the 256 partials in fixed order (deterministic)
        if (is_last) {
            volatile float* gp = g_partial;
            float v = 0.0f;
            #pragma unroll
            for (int k = 0; k < GRID / 32; k++)
                v += gp[lane + 32 * k];
            #pragma unroll
            for (int d = 16; d >= 1; d >>= 1)
                v += __shfl_down_sync(FULLM, v, d);
            if (lane == 0) out[0] = v * (1.0f / (float)BATCH);
        }
    }
}

extern "C" void kernel_launch(void* const* d_in, const int* in_sizes, int n_in,
                              void* d_out, int out_size)
{
    const float* ranks  = (const float*)d_in[0];   // [B, C] f32
    const int*   labels = (const int*)d_in[1];     // [B, C] i32
    const void*  ids    = d_in[2];                 // [L] i64 or i32 (sniffed)
    float* out = (float*)d_out;                    // [1] f32

    ranking_loss_kernel<<<GRID, NT>>>(ranks, labels, ids, out);
}